// round 16
// baseline (speedup 1.0000x reference)
#include <cuda_runtime.h>
#include <cuda_fp16.h>
#include <cstdint>

#define Bb 4
#define Nn 2048
#define Cc 256
#define OO 256
#define Ss 32
#define BP (Bb*Nn)            // 8192
#define Ee (BP*Ss)            // 262144
#define K1 259

#define HMINf (-0.02f)
#define HMAXf (0.04f)
#define EPSf  (1e-5f)
#define INVCNT (1.0f/(float)Ee)
#define NSM 148
#define FXS 1048576.0f        // 2^20 fixed-point scale
#define FXI (1.0f/1048576.0f)

// ---------------- static device scratch (allocation-free rule) ----------------
__device__ __half d_W2h [OO*Cc];            // fp16 W2, k-slot-permuted: [o][p(c)]
__device__ __half d_W1h [OO*Cc];            // fp16 W1 feature part, k-slot-permuted
__device__ __half d_ftT [(size_t)Bb*Nn*Cc]; // feat transposed fp16: [b][n][p(c)]
__device__ int    d_idx [BP*Ss];            // neighbor indices
__device__ __half d_F1h [(size_t)Bb*Nn*OO]; // F1[b][n][o] fp16  (4MB, L2-resident)
__device__ int                d_cnt[Bb*Nn];         // scatter: selection count per (b,n)
__device__ unsigned long long d_Wx[Bb*Nn], d_Wy[Bb*Nn], d_Wz[Bb*Nn];  // fixed-point scatter
__device__ unsigned long long d_Q[6];               // global gx²,gy²,gz²,gxgy,gxgz,gygz
__device__ float  d_pw [64*5*OO];                   // k_wsum partials: {cF,cF2,WxF,WyF,WzF}
__device__ float  d_pg [64*3];                      // k_wsum partials: {ΣWx,ΣWy,ΣWz}
__device__ float  d_ps2s[BP*OO], d_ps2q[BP*OO];     // stage-2 partial sums
__device__ float  d_mx2 [BP*OO], d_mn2 [BP*OO];     // per-(bp,o) max/min of y2 over s
__device__ float  d_pp  [4*32*OO];                  // level-2 partials (stage-2 uses [2],[3])

__device__ __forceinline__ unsigned long long fxq(float v){
    return (unsigned long long)(long long)llrintf(v * FXS);
}

// k-slot permutation: one thread's 4-half mma fragment = one contiguous 8B load.
__device__ __forceinline__ int kperm(int c){
    int c16 = c & 15;
    int q  = (c16 & 7) >> 1;
    int r  = c16 & 1;
    int hi = (c16 >> 3) & 1;
    return (c & ~15) | (q*4 + hi*2 + r);
}

// ---------------- K0: fused weight prep + feat transpose ----------------
__global__ void __launch_bounds__(256) k_wtr(const float* __restrict__ W1,
                                             const float* __restrict__ W2,
                                             const float* __restrict__ feat){
    if (blockIdx.x < 256){
        int i = blockIdx.x*256 + threadIdx.x;      // i = o*256 + c
        int o = i >> 8, c = i & 255;
        d_W1h[o*Cc + kperm(c)] = __float2half_rn(W1[o*K1 + 3 + c]);
        d_W2h[o*Cc + kperm(c)] = __float2half_rn(W2[i]);
        return;
    }
    int blk = blockIdx.x - 256;           // b(4) x ct(8) x nt(64)
    int b  = blk >> 9;
    int ct = (blk >> 6) & 7;
    int nt = blk & 63;
    int n0 = nt*32, c0 = ct*32;
    __shared__ float tsh[32][33];
    int t = threadIdx.x;
    {
        int cr = t >> 3, nq = (t & 7)*4;
        const float4 v = *(const float4*)(feat + ((size_t)b*Cc + c0 + cr)*Nn + n0 + nq);
        tsh[cr][nq+0] = v.x; tsh[cr][nq+1] = v.y; tsh[cr][nq+2] = v.z; tsh[cr][nq+3] = v.w;
    }
    __syncthreads();
    {
        int n = t >> 3, cl = (t & 7)*4;
        __half* dst = d_ftT + ((size_t)b*Nn + n0 + n)*Cc;
        #pragma unroll
        for (int w = 0; w < 2; w++){
            int cg = c0 + cl + w*2;            // even
            __half2 hv = __floats2half2_rn(tsh[cl + w*2][n], tsh[cl + w*2 + 1][n]);
            *(__half2*)(dst + kperm(cg)) = hv;
        }
    }
}

// ---------------- K0b: zero the scatter fields ----------------
__global__ void k_zero(){
    int i = blockIdx.x*256 + threadIdx.x;     // 0..8191
    d_cnt[i] = 0;
    d_Wx[i] = 0ull; d_Wy[i] = 0ull; d_Wz[i] = 0ull;
    if (i < 6) d_Q[i] = 0ull;
}

// ---------------- K1: cylinder query + stats scatter (one warp per (b,p)) ----------------
__global__ void k_idx(const float* __restrict__ xyz, const float* __restrict__ rot){
    int bp   = blockIdx.x*8 + (threadIdx.x >> 5);
    int lane = threadIdx.x & 31;
    int b = bp >> 11;
    const float* R = rot + (size_t)bp*9;
    float r00=R[0],r01=R[1],r02=R[2],r10=R[3],r11=R[4],r12=R[5],r20=R[6],r21=R[7],r22=R[8];
    const float* cc = xyz + (size_t)bp*3;
    float cx=cc[0], cy=cc[1], cz=cc[2];
    const float R2v = (float)(0.05*0.05);
    int count = 0, firstn = 0;
    bool have = false;
    float qxx=0.f,qyy=0.f,qzz=0.f,qxy=0.f,qxz=0.f,qyz=0.f;
    for (int base = 0; base < Nn && count < Ss; base += 32){
        int n = base + lane;
        const float* q = xyz + ((size_t)b*Nn + n)*3;
        float dx=q[0]-cx, dy=q[1]-cy, dz=q[2]-cz;
        float a0 = r00*dx + r01*dy + r02*dz;
        float a1 = r10*dx + r11*dy + r12*dz;
        float a2 = r20*dx + r21*dy + r22*dz;
        bool m = (a1*a1 + a2*a2 < R2v) & (a0 > HMINf) & (a0 < HMAXf);
        unsigned bal = __ballot_sync(0xffffffffu, m);
        if (!have && bal){ firstn = base + (__ffs(bal) - 1); have = true; }
        int pre = __popc(bal & ((1u << lane) - 1u));
        if (m && count + pre < Ss){
            d_idx[bp*Ss + count + pre] = n;
            // grouped geometry: g_k = sum_j (d_j/0.05) * rot[j][k]
            float vx = dx*20.f, vy = dy*20.f, vz = dz*20.f;
            float gx = vx*r00 + vy*r10 + vz*r20;
            float gy = vx*r01 + vy*r11 + vz*r21;
            float gz = vx*r02 + vy*r12 + vz*r22;
            int ix = b*Nn + n;
            atomicAdd(&d_cnt[ix], 1);
            atomicAdd(&d_Wx[ix], fxq(gx));
            atomicAdd(&d_Wy[ix], fxq(gy));
            atomicAdd(&d_Wz[ix], fxq(gz));
            qxx = fmaf(gx,gx,qxx); qyy = fmaf(gy,gy,qyy); qzz = fmaf(gz,gz,qzz);
            qxy = fmaf(gx,gy,qxy); qxz = fmaf(gx,gz,qxz); qyz = fmaf(gy,gz,qyz);
        }
        count += __popc(bal);
    }
    if (count < Ss){
        for (int j = count + lane; j < Ss; j += 32) d_idx[bp*Ss + j] = firstn;
        if (lane == 0){
            float pad = (float)(Ss - count);
            const float* q = xyz + ((size_t)b*Nn + firstn)*3;
            float dx=q[0]-cx, dy=q[1]-cy, dz=q[2]-cz;
            float vx = dx*20.f, vy = dy*20.f, vz = dz*20.f;
            float gx = vx*r00 + vy*r10 + vz*r20;
            float gy = vx*r01 + vy*r11 + vz*r21;
            float gz = vx*r02 + vy*r12 + vz*r22;
            int ix = b*Nn + firstn;
            atomicAdd(&d_cnt[ix], Ss - count);
            atomicAdd(&d_Wx[ix], fxq(gx*pad));
            atomicAdd(&d_Wy[ix], fxq(gy*pad));
            atomicAdd(&d_Wz[ix], fxq(gz*pad));
            qxx = fmaf(pad*gx,gx,qxx); qyy = fmaf(pad*gy,gy,qyy); qzz = fmaf(pad*gz,gz,qzz);
            qxy = fmaf(pad*gx,gy,qxy); qxz = fmaf(pad*gx,gz,qxz); qyz = fmaf(pad*gy,gz,qyz);
        }
    }
    // warp-reduce quads, one fixed-point atomic per warp per scalar
    #pragma unroll
    for (int msk = 16; msk; msk >>= 1){
        qxx += __shfl_xor_sync(0xffffffffu, qxx, msk);
        qyy += __shfl_xor_sync(0xffffffffu, qyy, msk);
        qzz += __shfl_xor_sync(0xffffffffu, qzz, msk);
        qxy += __shfl_xor_sync(0xffffffffu, qxy, msk);
        qxz += __shfl_xor_sync(0xffffffffu, qxz, msk);
        qyz += __shfl_xor_sync(0xffffffffu, qyz, msk);
    }
    if (lane == 0){
        atomicAdd(&d_Q[0], fxq(qxx));
        atomicAdd(&d_Q[1], fxq(qyy));
        atomicAdd(&d_Q[2], fxq(qzz));
        atomicAdd(&d_Q[3], fxq(qxy));
        atomicAdd(&d_Q[4], fxq(qxz));
        atomicAdd(&d_Q[5], fxq(qyz));
    }
}

// ---------------- fp16 mma helper ----------------
__device__ __forceinline__ void mma_f16(float& d0, float& d1, float& d2, float& d3,
                                        uint32_t a0, uint32_t a1, uint32_t a2, uint32_t a3,
                                        uint32_t b0, uint32_t b1){
    asm volatile("mma.sync.aligned.m16n8k16.row.col.f32.f16.f16.f32 "
                 "{%0,%1,%2,%3}, {%4,%5,%6,%7}, {%8,%9}, {%0,%1,%2,%3};\n"
                 : "+f"(d0), "+f"(d1), "+f"(d2), "+f"(d3)
                 : "r"(a0), "r"(a1), "r"(a2), "r"(a3), "r"(b0), "r"(b1));
}

#define HSTR 272   // halfs: 136 words == 8 (mod 32) -> conflict-free LDS.64 frags

// ---------------- K2: F1 on tensor cores ----------------
#define F1_SMEM (34816 + 139264)
__global__ void __launch_bounds__(256) k_F1mma(){
    extern __shared__ __align__(16) char sm1[];
    __half* Mt = (__half*)sm1;                   // ftT tile [64][HSTR]
    __half* Nw = (__half*)(sm1 + 34816);         // W1h [256][HSTR]
    int tid = threadIdx.x;
    int blk = blockIdx.x;                        // 128 = b(4) x nt(32)
    int b  = blk >> 5;
    int n0 = (blk & 31) * 64;

    #pragma unroll
    for (int k = 0; k < 32; k++){
        int i = tid + k*256;
        int row = i >> 5, seg = i & 31;
        uint32_t d = (uint32_t)__cvta_generic_to_shared(Nw + row*HSTR + seg*8);
        asm volatile("cp.async.cg.shared.global [%0], [%1], 16;\n"
                     :: "r"(d), "l"(d_W1h + (size_t)row*Cc + seg*8));
    }
    #pragma unroll
    for (int k = 0; k < 8; k++){
        int i = tid + k*256;
        int row = i >> 5, seg = i & 31;
        uint32_t d = (uint32_t)__cvta_generic_to_shared(Mt + row*HSTR + seg*8);
        asm volatile("cp.async.cg.shared.global [%0], [%1], 16;\n"
                     :: "r"(d), "l"(d_ftT + ((size_t)b*Nn + n0 + row)*Cc + seg*8));
    }
    asm volatile("cp.async.commit_group;\n" ::: "memory");
    asm volatile("cp.async.wait_group 0;\n" ::: "memory");
    __syncthreads();

    int lane = tid & 31, w = tid >> 5;
    int q = lane & 3, g = lane >> 2;
    int obase = w * 32;

    float acc[4][4][4];
    #pragma unroll
    for (int mt = 0; mt < 4; mt++)
        #pragma unroll
        for (int ot = 0; ot < 4; ot++)
            #pragma unroll
            for (int k = 0; k < 4; k++) acc[mt][ot][k] = 0.f;

    const char* Mrow = (const char*)(Mt + (size_t)g*HSTR);
    const char* Nrow = (const char*)(Nw + (size_t)(obase + g)*HSTR);

    #pragma unroll 4
    for (int kt = 0; kt < 16; kt++){
        int ko = kt*32 + q*8;
        uint2 ma[4][2];
        #pragma unroll
        for (int mt = 0; mt < 4; mt++){
            ma[mt][0] = *(const uint2*)(Mrow + (mt*16    )*HSTR*2 + ko);
            ma[mt][1] = *(const uint2*)(Mrow + (mt*16 + 8)*HSTR*2 + ko);
        }
        #pragma unroll
        for (int ot = 0; ot < 4; ot++){
            uint2 nb = *(const uint2*)(Nrow + (ot*8)*HSTR*2 + ko);
            #pragma unroll
            for (int mt = 0; mt < 4; mt++){
                mma_f16(acc[mt][ot][0], acc[mt][ot][1], acc[mt][ot][2], acc[mt][ot][3],
                        ma[mt][0].x, ma[mt][1].x, ma[mt][0].y, ma[mt][1].y, nb.x, nb.y);
            }
        }
    }

    #pragma unroll
    for (int mt = 0; mt < 4; mt++){
        #pragma unroll
        for (int ot = 0; ot < 4; ot++){
            int o = obase + ot*8 + 2*q;
            int n = n0 + mt*16 + g;
            __half* dst = d_F1h + ((size_t)b*Nn + n)*OO + o;
            *(__half2*)dst = __floats2half2_rn(acc[mt][ot][0], acc[mt][ot][1]);
            *(__half2*)(dst + 8*OO) = __floats2half2_rn(acc[mt][ot][2], acc[mt][ot][3]);
        }
    }
}

// ---------------- K3: weighted F1 reduction (replaces the gather-based stats1) ----------
__global__ void __launch_bounds__(256) k_wsum(){
    int z = blockIdx.x;                   // 64 blocks x 128 rows
    int o = threadIdx.x;
    float sF=0.f, sF2=0.f, sWx=0.f, sWy=0.f, sWz=0.f;
    float gx=0.f, gy=0.f, gz=0.f;
    for (int k = 0; k < 128; k++){
        int m = z*128 + k;                // global (b,n) row
        float F  = __half2float(d_F1h[(size_t)m*OO + o]);
        float c  = (float)d_cnt[m];
        float wx = (float)(long long)d_Wx[m] * FXI;
        float wy = (float)(long long)d_Wy[m] * FXI;
        float wz = (float)(long long)d_Wz[m] * FXI;
        float cF = c*F;
        sF  += cF;
        sF2  = fmaf(cF, F, sF2);
        sWx  = fmaf(wx, F, sWx);
        sWy  = fmaf(wy, F, sWy);
        sWz  = fmaf(wz, F, sWz);
        if (o == 0){ gx += wx; gy += wy; gz += wz; }
    }
    d_pw[(z*5+0)*OO + o] = sF;
    d_pw[(z*5+1)*OO + o] = sF2;
    d_pw[(z*5+2)*OO + o] = sWx;
    d_pw[(z*5+3)*OO + o] = sWy;
    d_pw[(z*5+4)*OO + o] = sWz;
    if (o == 0){ d_pg[z*3+0]=gx; d_pg[z*3+1]=gy; d_pg[z*3+2]=gz; }
}

// ---------------- deterministic two-level reduction (stage 2) ----------------
__global__ void k_red_a(){
    int which = 2 + blockIdx.y;                  // 2..3
    const float* src = (which == 2) ? d_ps2s : d_ps2q;
    float* dst = d_pp + which*(32*OO);
    int z = blockIdx.x;                          // 0..31
    int o = threadIdx.x;
    float s = 0.f;
    for (int k = 0; k < 256; k++)
        s += src[((size_t)(z*256 + k))*OO + o];
    dst[z*OO + o] = s;
}

// smem layout (bytes) for conv2 (double-buffered h, 2-bp groups):
#define OFF_A   69632                 // 2 x h[64][HSTR] halfs = 69632 before it
#define OFF_IDX 208896                // A: 256*HSTR*2 = 139264
#define OFF_G   209408                // 2 x 3 x 64 floats = 1536
#define OFF_SC1 210944
#define OFF_SF1 211968
#define SMEMB   212992

// geometry for one 2-bp group into the given buffers (threads 0..63)
__device__ __forceinline__ void geom2(const float* __restrict__ xyz,
                                      const float* __restrict__ rot,
                                      int grp, int tid, int* idxd,
                                      float* gx, float* gy, float* gz){
    if (tid < 64){
        int s  = tid;
        int bp = grp*2 + (s >> 5);
        int b  = bp >> 11;
        int i  = d_idx[bp*Ss + (s & 31)];
        idxd[s] = i;
        const float* R = rot + (size_t)bp*9;
        const float* c = xyz + (size_t)bp*3;
        const float* pt = xyz + ((size_t)b*Nn + i)*3;
        float vx = (pt[0]-c[0]) / 0.05f;
        float vy = (pt[1]-c[1]) / 0.05f;
        float vz = (pt[2]-c[2]) / 0.05f;
        gx[s] = vx*R[0] + vy*R[3] + vz*R[6];
        gy[s] = vx*R[1] + vy*R[4] + vz*R[7];
        gz[s] = vx*R[2] + vy*R[5] + vz*R[8];
    }
}

// build h tile for one 2-bp group (all 512 threads; 2 channels x 16 s each)
__device__ __forceinline__ void hbuild2(const float* __restrict__ W1, __half* hdst,
                                        const int* idxd, const float* gx,
                                        const float* gy, const float* gz,
                                        const float* s_sc1, const float* s_sf1,
                                        int grp, int tid){
    int cpair = tid & 127;
    int c0    = cpair*2;
    int sbase = (tid >> 7) * 16;
    int b     = (grp*2) >> 11;
    int p     = kperm(c0);
    float wa0 = W1[c0*K1+0],     wa1 = W1[c0*K1+1],     wa2 = W1[c0*K1+2];
    float wb0 = W1[(c0+1)*K1+0], wb1 = W1[(c0+1)*K1+1], wb2 = W1[(c0+1)*K1+2];
    float sca = s_sc1[c0],   sfa = s_sf1[c0];
    float scb = s_sc1[c0+1], sfb = s_sf1[c0+1];
    const __half2* F1b2 = (const __half2*)(d_F1h + (size_t)b*Nn*OO);
    #pragma unroll 4
    for (int ds = 0; ds < 16; ds++){
        int s = sbase + ds;
        float2 f = __half22float2(F1b2[(size_t)idxd[s]*128 + cpair]);
        float va = fmaf(wa0, gx[s], fmaf(wa1, gy[s], fmaf(wa2, gz[s], f.x)));
        float vb = fmaf(wb0, gx[s], fmaf(wb1, gy[s], fmaf(wb2, gz[s], f.y)));
        va = fmaxf(fmaf(va, sca, sfa), 0.f);
        vb = fmaxf(fmaf(vb, scb, sfb), 0.f);
        *(__half2*)(hdst + s*HSTR + p) = __floats2half2_rn(va, vb);
    }
}

// ---------------- K4: persistent conv2, double-buffered h (2-bp groups) ----------------
__global__ void __launch_bounds__(512, 1) k_conv2(const float* __restrict__ xyz,
                                                  const float* __restrict__ rot,
                                                  const float* __restrict__ W1,
                                                  const float* __restrict__ gamma1,
                                                  const float* __restrict__ beta1){
    extern __shared__ __align__(16) char smraw[];
    __half* h16  = (__half*)smraw;                 // 2 x [64][HSTR]
    __half* Asm  = (__half*)(smraw + OFF_A);       // [256][HSTR]
    int*    idxb = (int*)(smraw + OFF_IDX);        // 2 x [64]
    float*  gbuf = (float*)(smraw + OFF_G);        // 2 x 3 x [64]
    float*  s_sc1 = (float*)(smraw + OFF_SC1);     // [256]
    float*  s_sf1 = (float*)(smraw + OFF_SF1);     // [256]

    int tid = threadIdx.x;
    int lane = tid & 31, w = tid >> 5;
    int q = lane & 3, g = lane >> 2;
    int obase = (w & 7) * 32;                      // 8 warp-cols cover 256 o
    int warpS = (w >> 3) * 32;                     // 2 warp-rows cover 64 s (= 2 bp)

    // ---- load ALL of W2 into smem once ----
    #pragma unroll
    for (int k = 0; k < 16; k++){
        int i = tid + k*512;
        int row = i >> 5, seg = i & 31;
        uint32_t d = (uint32_t)__cvta_generic_to_shared(Asm + row*HSTR + seg*8);
        asm volatile("cp.async.cg.shared.global [%0], [%1], 16;\n"
                     :: "r"(d), "l"(d_W2h + (size_t)row*Cc + seg*8));
    }
    asm volatile("cp.async.commit_group;\n" ::: "memory");

    // ---- fused BN1 stats from factored sums (overlaps cp.async) ----
    if (tid < 256){
        int o = tid;
        float sF=0.f, sF2=0.f, sWxF=0.f, sWyF=0.f, sWzF=0.f;
        float Gx=0.f, Gy=0.f, Gz=0.f;
        #pragma unroll 4
        for (int z = 0; z < 64; z++){
            sF   += d_pw[(z*5+0)*OO + o];
            sF2  += d_pw[(z*5+1)*OO + o];
            sWxF += d_pw[(z*5+2)*OO + o];
            sWyF += d_pw[(z*5+3)*OO + o];
            sWzF += d_pw[(z*5+4)*OO + o];
            Gx += d_pg[z*3+0]; Gy += d_pg[z*3+1]; Gz += d_pg[z*3+2];
        }
        float Qxx = (float)(long long)d_Q[0] * FXI;
        float Qyy = (float)(long long)d_Q[1] * FXI;
        float Qzz = (float)(long long)d_Q[2] * FXI;
        float Qxy = (float)(long long)d_Q[3] * FXI;
        float Qxz = (float)(long long)d_Q[4] * FXI;
        float Qyz = (float)(long long)d_Q[5] * FXI;
        float w0 = W1[o*K1+0], w1 = W1[o*K1+1], w2 = W1[o*K1+2];
        float S1 = sF + w0*Gx + w1*Gy + w2*Gz;
        float S2 = sF2 + 2.f*(w0*sWxF + w1*sWyF + w2*sWzF)
                 + w0*w0*Qxx + w1*w1*Qyy + w2*w2*Qzz
                 + 2.f*(w0*w1*Qxy + w0*w2*Qxz + w1*w2*Qyz);
        float mu  = S1 * INVCNT;
        float var = S2 * INVCNT - mu*mu;
        float sc  = rsqrtf(var + EPSf) * gamma1[o];
        s_sc1[o] = sc;
        s_sf1[o] = beta1[o] - mu*sc;
    }

    const char* Arow = (const char*)(Asm + (size_t)(obase + g)*HSTR);
    const int NG = BP/2;                           // 4096 groups of 2 bp

    // prologue: geom(g0) ; sync ; hbuild(g0) + geom(g1) ; sync
    int g0 = blockIdx.x;
    geom2(xyz, rot, g0, tid, idxb, gbuf, gbuf+128, gbuf+256);
    __syncthreads();
    hbuild2(W1, h16, idxb, gbuf, gbuf+128, gbuf+256, s_sc1, s_sf1, g0, tid);
    if (g0 + NSM < NG)
        geom2(xyz, rot, g0 + NSM, tid, idxb+64, gbuf+64, gbuf+192, gbuf+320);
    asm volatile("cp.async.wait_group 0;\n" ::: "memory");
    __syncthreads();

    int par = 0;
    for (int gi = g0; gi < NG; gi += NSM){
        int np = par ^ 1;
        if (gi + NSM < NG)
            hbuild2(W1, h16 + np*64*HSTR, idxb + np*64,
                    gbuf + np*64, gbuf + 128 + np*64, gbuf + 256 + np*64,
                    s_sc1, s_sf1, gi + NSM, tid);
        if (gi + 2*NSM < NG)
            geom2(xyz, rot, gi + 2*NSM, tid, idxb + par*64,
                  gbuf + par*64, gbuf + 128 + par*64, gbuf + 256 + par*64);

        const char* Bsm = (const char*)(h16 + (size_t)par*64*HSTR + (size_t)(warpS + g)*HSTR);
        float acc[2][4][4];
        #pragma unroll
        for (int i = 0; i < 2; i++)
            #pragma unroll
            for (int j = 0; j < 4; j++)
                #pragma unroll
                for (int k = 0; k < 4; k++) acc[i][j][k] = 0.f;

        #pragma unroll 4
        for (int kt = 0; kt < 16; kt++){
            uint2 fa0 = *(const uint2*)(Arow +             0 + kt*32 + q*8);
            uint2 fa1 = *(const uint2*)(Arow +  8*HSTR*2      + kt*32 + q*8);
            uint2 fa2 = *(const uint2*)(Arow + 16*HSTR*2      + kt*32 + q*8);
            uint2 fa3 = *(const uint2*)(Arow + 24*HSTR*2      + kt*32 + q*8);
            #pragma unroll
            for (int j = 0; j < 4; j++){
                uint2 bv = *(const uint2*)(Bsm + j*(8*HSTR*2) + kt*32 + q*8);
                mma_f16(acc[0][j][0], acc[0][j][1], acc[0][j][2], acc[0][j][3],
                        fa0.x, fa1.x, fa0.y, fa1.y, bv.x, bv.y);
                mma_f16(acc[1][j][0], acc[1][j][1], acc[1][j][2], acc[1][j][3],
                        fa2.x, fa3.x, fa2.y, fa3.y, bv.x, bv.y);
            }
        }

        int bp = gi*2 + (w >> 3);
        #pragma unroll
        for (int i = 0; i < 2; i++){
            float s0=0.f, q0=0.f, mx0=-3.4e38f, mn0=3.4e38f;
            float s1=0.f, q1=0.f, mx1=-3.4e38f, mn1=3.4e38f;
            #pragma unroll
            for (int j4 = 0; j4 < 4; j4++){
                const float* a = acc[i][j4];
                s0 += a[0] + a[1];
                q0  = fmaf(a[0], a[0], fmaf(a[1], a[1], q0));
                mx0 = fmaxf(mx0, fmaxf(a[0], a[1]));
                mn0 = fminf(mn0, fminf(a[0], a[1]));
                s1 += a[2] + a[3];
                q1  = fmaf(a[2], a[2], fmaf(a[3], a[3], q1));
                mx1 = fmaxf(mx1, fmaxf(a[2], a[3]));
                mn1 = fminf(mn1, fminf(a[2], a[3]));
            }
            #pragma unroll
            for (int msk = 1; msk <= 2; msk <<= 1){
                s0 += __shfl_xor_sync(0xffffffffu, s0, msk);
                q0 += __shfl_xor_sync(0xffffffffu, q0, msk);
                mx0 = fmaxf(mx0, __shfl_xor_sync(0xffffffffu, mx0, msk));
                mn0 = fminf(mn0, __shfl_xor_sync(0xffffffffu, mn0, msk));
                s1 += __shfl_xor_sync(0xffffffffu, s1, msk);
                q1 += __shfl_xor_sync(0xffffffffu, q1, msk);
                mx1 = fmaxf(mx1, __shfl_xor_sync(0xffffffffu, mx1, msk));
                mn1 = fminf(mn1, __shfl_xor_sync(0xffffffffu, mn1, msk));
            }
            if (q == 0){
                int o0 = obase + 16*i + g;
                size_t ix0 = (size_t)bp*OO + o0;
                d_ps2s[ix0] = s0; d_ps2q[ix0] = q0; d_mx2[ix0] = mx0; d_mn2[ix0] = mn0;
                size_t ix1 = ix0 + 8;
                d_ps2s[ix1] = s1; d_ps2q[ix1] = q1; d_mx2[ix1] = mx1; d_mn2[ix1] = mn1;
            }
        }
        __syncthreads();
        par = np;
    }
}

// ---------------- K5: BN2 final reduce + relu + max via monotonicity ----------------
__global__ void __launch_bounds__(256) k_final(const float* __restrict__ gamma,
                                               const float* __restrict__ beta,
                                               float* __restrict__ out){
    int blk = blockIdx.x;                 // 256 blocks, 32 p's each
    int bp0 = blk * 32;
    int b = bp0 >> 11;
    int pbase = bp0 & 2047;
    int tid = threadIdx.x;
    __shared__ float sh[256*33];

    int o = tid;
    float s = 0.f, qv = 0.f;
    #pragma unroll 8
    for (int z = 0; z < 32; z++){
        s  += d_pp[2*(32*OO) + z*OO + o];
        qv += d_pp[3*(32*OO) + z*OO + o];
    }
    float mu  = s * INVCNT;
    float var = qv * INVCNT - mu*mu;
    float sc  = rsqrtf(var + EPSf) * gamma[o];
    float sf  = beta[o] - mu*sc;

    for (int p = 0; p < 32; p++){
        size_t ix = (size_t)(bp0 + p)*OO + o;
        float mx = d_mx2[ix], mn = d_mn2[ix];
        float m = (sc >= 0.f) ? mx : mn;
        sh[o*33 + p] = fmaxf(fmaf(m, sc, sf), 0.f);
    }
    __syncthreads();

    int p   = tid & 31;
    int og0 = (tid >> 5) * 32;
    #pragma unroll
    for (int k = 0; k < 32; k++){
        int o2 = og0 + k;
        out[((size_t)(b*OO + o2))*Nn + pbase + p] = sh[o2*33 + p];
    }
}

// ---------------- launcher ----------------
extern "C" void kernel_launch(void* const* d_in, const int* in_sizes, int n_in,
                              void* d_out, int out_size){
    (void)in_sizes; (void)n_in; (void)out_size;
    const float* xyz  = (const float*)d_in[0];
    const float* feat = (const float*)d_in[1];
    const float* rot  = (const float*)d_in[2];
    const float* W1   = (const float*)d_in[3];
    const float* g1   = (const float*)d_in[4];
    const float* b1   = (const float*)d_in[5];
    const float* W2   = (const float*)d_in[6];
    const float* g2   = (const float*)d_in[7];
    const float* b2   = (const float*)d_in[8];
    float* out = (float*)d_out;

    static bool s_init = false;
    static cudaStream_t s2;
    static cudaEvent_t evA, evB;
    if (!s_init){
        cudaStreamCreateWithFlags(&s2, cudaStreamNonBlocking);
        cudaEventCreateWithFlags(&evA, cudaEventDisableTiming);
        cudaEventCreateWithFlags(&evB, cudaEventDisableTiming);
        cudaFuncSetAttribute(k_conv2, cudaFuncAttributeMaxDynamicSharedMemorySize, SMEMB);
        cudaFuncSetAttribute(k_F1mma, cudaFuncAttributeMaxDynamicSharedMemorySize, F1_SMEM);
        s_init = true;
    }

    // fork: zero + k_idx(+scatter) on side stream, concurrent with weight prep + F1 GEMM
    cudaEventRecord(evA, 0);
    cudaStreamWaitEvent(s2, evA, 0);
    k_zero<<<32, 256, 0, s2>>>();
    k_idx <<<BP/8, 256, 0, s2>>>(xyz, rot);
    cudaEventRecord(evB, s2);

    k_wtr  <<<256 + 2048, 256>>>(W1, W2, feat);
    k_F1mma<<<128, 256, F1_SMEM>>>();

    // join: wsum needs scatter fields + F1
    cudaStreamWaitEvent(0, evB, 0);

    k_wsum <<<64, 256>>>();
    k_conv2<<<NSM, 512, SMEMB>>>(xyz, rot, W1, g1, b1);
    k_red_a<<<dim3(32,2), 256>>>();
    k_final<<<BP/32, 256>>>(g2, b2, out);
}

// round 17
// speedup vs baseline: 1.0900x; 1.0900x over previous
#include <cuda_runtime.h>
#include <cuda_fp16.h>
#include <cstdint>

#define Bb 4
#define Nn 2048
#define Cc 256
#define OO 256
#define Ss 32
#define BP (Bb*Nn)            // 8192
#define Ee (BP*Ss)            // 262144
#define K1 259

#define HMINf (-0.02f)
#define HMAXf (0.04f)
#define EPSf  (1e-5f)
#define INVCNT (1.0f/(float)Ee)
#define NSM 148

// ---------------- static device scratch (allocation-free rule) ----------------
__device__ __half d_W2h [OO*Cc];            // fp16 W2, k-slot-permuted: [o][p(c)]
__device__ __half d_W1h [OO*Cc];            // fp16 W1 feature part, k-slot-permuted
__device__ __half d_ftT [(size_t)Bb*Nn*Cc]; // feat transposed fp16: [b][n][p(c)]
__device__ int    d_idx [BP*Ss];            // neighbor indices
__device__ __half d_F1h [(size_t)Bb*Nn*OO]; // F1[b][n][o] fp16  (4MB, L2-resident)
__device__ float  d_ps1s[BP*OO], d_ps1q[BP*OO];   // stage-1 partial sums
__device__ float  d_p2s [NSM*2*OO], d_p2q [NSM*2*OO]; // stage-2 per-warprow partials
__device__ float  d_mx2 [BP*OO], d_mn2 [BP*OO];   // per-(bp,o) max/min of y2 over s
__device__ float  d_pp  [4*32*OO];                // level-2 partials

// k-slot permutation: one thread's 4-half mma fragment = one contiguous 8B load.
__device__ __forceinline__ int kperm(int c){
    int c16 = c & 15;
    int q  = (c16 & 7) >> 1;
    int r  = c16 & 1;
    int hi = (c16 >> 3) & 1;
    return (c & ~15) | (q*4 + hi*2 + r);
}

// ---------------- K0: fused weight prep + feat transpose ----------------
__global__ void __launch_bounds__(256) k_wtr(const float* __restrict__ W1,
                                             const float* __restrict__ W2,
                                             const float* __restrict__ feat){
    if (blockIdx.x < 256){
        int i = blockIdx.x*256 + threadIdx.x;      // i = o*256 + c
        int o = i >> 8, c = i & 255;
        d_W1h[o*Cc + kperm(c)] = __float2half_rn(W1[o*K1 + 3 + c]);
        d_W2h[o*Cc + kperm(c)] = __float2half_rn(W2[i]);
        return;
    }
    int blk = blockIdx.x - 256;           // b(4) x ct(8) x nt(64)
    int b  = blk >> 9;
    int ct = (blk >> 6) & 7;
    int nt = blk & 63;
    int n0 = nt*32, c0 = ct*32;
    __shared__ float tsh[32][33];
    int t = threadIdx.x;
    {
        int cr = t >> 3, nq = (t & 7)*4;
        const float4 v = *(const float4*)(feat + ((size_t)b*Cc + c0 + cr)*Nn + n0 + nq);
        tsh[cr][nq+0] = v.x; tsh[cr][nq+1] = v.y; tsh[cr][nq+2] = v.z; tsh[cr][nq+3] = v.w;
    }
    __syncthreads();
    {
        int n = t >> 3, cl = (t & 7)*4;
        __half* dst = d_ftT + ((size_t)b*Nn + n0 + n)*Cc;
        #pragma unroll
        for (int w = 0; w < 2; w++){
            int cg = c0 + cl + w*2;            // even
            __half2 hv = __floats2half2_rn(tsh[cl + w*2][n], tsh[cl + w*2 + 1][n]);
            *(__half2*)(dst + kperm(cg)) = hv;
        }
    }
}

// ---------------- K1: cylinder query (one warp per (b,p)) ----------------
__global__ void k_idx(const float* __restrict__ xyz, const float* __restrict__ rot){
    int bp   = blockIdx.x*8 + (threadIdx.x >> 5);
    int lane = threadIdx.x & 31;
    int b = bp >> 11;
    const float* R = rot + (size_t)bp*9;
    float r00=R[0],r01=R[1],r02=R[2],r10=R[3],r11=R[4],r12=R[5],r20=R[6],r21=R[7],r22=R[8];
    const float* cc = xyz + (size_t)bp*3;
    float cx=cc[0], cy=cc[1], cz=cc[2];
    const float R2v = (float)(0.05*0.05);
    int count = 0, firstn = 0;
    bool have = false;
    for (int base = 0; base < Nn && count < Ss; base += 32){
        int n = base + lane;
        const float* q = xyz + ((size_t)b*Nn + n)*3;
        float dx=q[0]-cx, dy=q[1]-cy, dz=q[2]-cz;
        float a0 = r00*dx + r01*dy + r02*dz;
        float a1 = r10*dx + r11*dy + r12*dz;
        float a2 = r20*dx + r21*dy + r22*dz;
        bool m = (a1*a1 + a2*a2 < R2v) & (a0 > HMINf) & (a0 < HMAXf);
        unsigned bal = __ballot_sync(0xffffffffu, m);
        if (!have && bal){ firstn = base + (__ffs(bal) - 1); have = true; }
        int pre = __popc(bal & ((1u << lane) - 1u));
        if (m && count + pre < Ss) d_idx[bp*Ss + count + pre] = n;
        count += __popc(bal);
    }
    if (count < Ss){
        for (int j = count + lane; j < Ss; j += 32) d_idx[bp*Ss + j] = firstn;
    }
}

// ---------------- fp16 mma helper ----------------
__device__ __forceinline__ void mma_f16(float& d0, float& d1, float& d2, float& d3,
                                        uint32_t a0, uint32_t a1, uint32_t a2, uint32_t a3,
                                        uint32_t b0, uint32_t b1){
    asm volatile("mma.sync.aligned.m16n8k16.row.col.f32.f16.f16.f32 "
                 "{%0,%1,%2,%3}, {%4,%5,%6,%7}, {%8,%9}, {%0,%1,%2,%3};\n"
                 : "+f"(d0), "+f"(d1), "+f"(d2), "+f"(d3)
                 : "r"(a0), "r"(a1), "r"(a2), "r"(a3), "r"(b0), "r"(b1));
}

#define HSTR 272   // halfs: 136 words == 8 (mod 32) -> conflict-free LDS.64 frags

// ---------------- K2: F1 on tensor cores ----------------
#define F1_SMEM (34816 + 139264)
__global__ void __launch_bounds__(256) k_F1mma(){
    extern __shared__ __align__(16) char sm1[];
    __half* Mt = (__half*)sm1;                   // ftT tile [64][HSTR]
    __half* Nw = (__half*)(sm1 + 34816);         // W1h [256][HSTR]
    int tid = threadIdx.x;
    int blk = blockIdx.x;                        // 128 = b(4) x nt(32)
    int b  = blk >> 5;
    int n0 = (blk & 31) * 64;

    #pragma unroll
    for (int k = 0; k < 32; k++){
        int i = tid + k*256;
        int row = i >> 5, seg = i & 31;
        uint32_t d = (uint32_t)__cvta_generic_to_shared(Nw + row*HSTR + seg*8);
        asm volatile("cp.async.cg.shared.global [%0], [%1], 16;\n"
                     :: "r"(d), "l"(d_W1h + (size_t)row*Cc + seg*8));
    }
    #pragma unroll
    for (int k = 0; k < 8; k++){
        int i = tid + k*256;
        int row = i >> 5, seg = i & 31;
        uint32_t d = (uint32_t)__cvta_generic_to_shared(Mt + row*HSTR + seg*8);
        asm volatile("cp.async.cg.shared.global [%0], [%1], 16;\n"
                     :: "r"(d), "l"(d_ftT + ((size_t)b*Nn + n0 + row)*Cc + seg*8));
    }
    asm volatile("cp.async.commit_group;\n" ::: "memory");
    asm volatile("cp.async.wait_group 0;\n" ::: "memory");
    __syncthreads();

    int lane = tid & 31, w = tid >> 5;
    int q = lane & 3, g = lane >> 2;
    int obase = w * 32;

    float acc[4][4][4];
    #pragma unroll
    for (int mt = 0; mt < 4; mt++)
        #pragma unroll
        for (int ot = 0; ot < 4; ot++)
            #pragma unroll
            for (int k = 0; k < 4; k++) acc[mt][ot][k] = 0.f;

    const char* Mrow = (const char*)(Mt + (size_t)g*HSTR);
    const char* Nrow = (const char*)(Nw + (size_t)(obase + g)*HSTR);

    #pragma unroll 4
    for (int kt = 0; kt < 16; kt++){
        int ko = kt*32 + q*8;
        uint2 ma[4][2];
        #pragma unroll
        for (int mt = 0; mt < 4; mt++){
            ma[mt][0] = *(const uint2*)(Mrow + (mt*16    )*HSTR*2 + ko);
            ma[mt][1] = *(const uint2*)(Mrow + (mt*16 + 8)*HSTR*2 + ko);
        }
        #pragma unroll
        for (int ot = 0; ot < 4; ot++){
            uint2 nb = *(const uint2*)(Nrow + (ot*8)*HSTR*2 + ko);
            #pragma unroll
            for (int mt = 0; mt < 4; mt++){
                mma_f16(acc[mt][ot][0], acc[mt][ot][1], acc[mt][ot][2], acc[mt][ot][3],
                        ma[mt][0].x, ma[mt][1].x, ma[mt][0].y, ma[mt][1].y, nb.x, nb.y);
            }
        }
    }

    #pragma unroll
    for (int mt = 0; mt < 4; mt++){
        #pragma unroll
        for (int ot = 0; ot < 4; ot++){
            int o = obase + ot*8 + 2*q;
            int n = n0 + mt*16 + g;
            __half* dst = d_F1h + ((size_t)b*Nn + n)*OO + o;
            *(__half2*)dst = __floats2half2_rn(acc[mt][ot][0], acc[mt][ot][1]);
            *(__half2*)(dst + 8*OO) = __floats2half2_rn(acc[mt][ot][2], acc[mt][ot][3]);
        }
    }
}

// ---------------- K3: stats of conv1 output, 2 bp per 256-thread block (R15 form) --------
__global__ void __launch_bounds__(256) k_stats1(const float* __restrict__ xyz,
                                                const float* __restrict__ rot,
                                                const float* __restrict__ W1){
    int sub = threadIdx.x >> 7;           // 0/1
    int t   = threadIdx.x & 127;
    int bp  = blockIdx.x*2 + sub;
    int b = bp >> 11;
    __shared__ int   idxs[2][32];
    __shared__ float gx[2][32], gy[2][32], gz[2][32];
    if (t < 32){
        int s = t;
        int i = d_idx[bp*Ss + s];
        idxs[sub][s] = i;
        const float* R = rot + (size_t)bp*9;
        const float* c = xyz + (size_t)bp*3;
        const float* q = xyz + ((size_t)b*Nn + i)*3;
        float vx = (q[0]-c[0]) / 0.05f;
        float vy = (q[1]-c[1]) / 0.05f;
        float vz = (q[2]-c[2]) / 0.05f;
        gx[sub][s] = vx*R[0] + vy*R[3] + vz*R[6];
        gy[sub][s] = vx*R[1] + vy*R[4] + vz*R[7];
        gz[sub][s] = vx*R[2] + vy*R[5] + vz*R[8];
    }
    __syncthreads();

    int c0 = t*2;
    float wa0 = W1[c0*K1+0],     wa1 = W1[c0*K1+1],     wa2 = W1[c0*K1+2];
    float wb0 = W1[(c0+1)*K1+0], wb1 = W1[(c0+1)*K1+1], wb2 = W1[(c0+1)*K1+2];
    const __half2* F1b2 = (const __half2*)(d_F1h + (size_t)b*Nn*OO);
    float lsa = 0.f, lqa = 0.f, lsb = 0.f, lqb = 0.f;
    #pragma unroll 8
    for (int s = 0; s < Ss; s++){
        __half2 hv = F1b2[(size_t)idxs[sub][s]*128 + t];
        float2 f = __half22float2(hv);
        float va = fmaf(wa0, gx[sub][s], fmaf(wa1, gy[sub][s], fmaf(wa2, gz[sub][s], f.x)));
        float vb = fmaf(wb0, gx[sub][s], fmaf(wb1, gy[sub][s], fmaf(wb2, gz[sub][s], f.y)));
        lsa += va;  lqa = fmaf(va, va, lqa);
        lsb += vb;  lqb = fmaf(vb, vb, lqb);
    }
    d_ps1s[bp*OO + c0]     = lsa;  d_ps1q[bp*OO + c0]     = lqa;
    d_ps1s[bp*OO + c0 + 1] = lsb;  d_ps1q[bp*OO + c0 + 1] = lqb;
}

// ---------------- deterministic two-level reduction (stage 1) ----------------
__global__ void k_red_a(){
    int which = blockIdx.y;                      // 0..1
    const float* src = (which == 0) ? d_ps1s : d_ps1q;
    float* dst = d_pp + which*(32*OO);
    int z = blockIdx.x;                          // 0..31
    int o = threadIdx.x;
    float s = 0.f;
    for (int k = 0; k < 256; k++)
        s += src[((size_t)(z*256 + k))*OO + o];
    dst[z*OO + o] = s;
}

// ---------------- stage-2 partial reducer: 296 rows -> 8 rows ----------------
__global__ void k_red2p(){
    int z = blockIdx.x;                   // 0..7
    int o = threadIdx.x;
    float s = 0.f, q = 0.f;
    #pragma unroll 4
    for (int k = 0; k < 37; k++){
        int r = z*37 + k;
        s += d_p2s[r*OO + o];
        q += d_p2q[r*OO + o];
    }
    d_pp[2*(32*OO) + z*OO + o] = s;
    d_pp[3*(32*OO) + z*OO + o] = q;
}

// smem layout (bytes) for conv2 (double-buffered h, 2-bp groups):
#define OFF_A   69632                 // 2 x h[64][HSTR] halfs = 69632 before it
#define OFF_IDX 208896                // A: 256*HSTR*2 = 139264
#define OFF_G   209408                // 2 x 3 x 64 floats = 1536
#define OFF_SC1 210944
#define OFF_SF1 211968
#define SMEMB   212992

// geometry for one 2-bp group into the given buffers (threads 0..63)
__device__ __forceinline__ void geom2(const float* __restrict__ xyz,
                                      const float* __restrict__ rot,
                                      int grp, int tid, int* idxd,
                                      float* gx, float* gy, float* gz){
    if (tid < 64){
        int s  = tid;
        int bp = grp*2 + (s >> 5);
        int b  = bp >> 11;
        int i  = d_idx[bp*Ss + (s & 31)];
        idxd[s] = i;
        const float* R = rot + (size_t)bp*9;
        const float* c = xyz + (size_t)bp*3;
        const float* pt = xyz + ((size_t)b*Nn + i)*3;
        float vx = (pt[0]-c[0]) / 0.05f;
        float vy = (pt[1]-c[1]) / 0.05f;
        float vz = (pt[2]-c[2]) / 0.05f;
        gx[s] = vx*R[0] + vy*R[3] + vz*R[6];
        gy[s] = vx*R[1] + vy*R[4] + vz*R[7];
        gz[s] = vx*R[2] + vy*R[5] + vz*R[8];
    }
}

// build h tile for one 2-bp group (all 512 threads; 2 channels x 16 s each)
__device__ __forceinline__ void hbuild2(const float* __restrict__ W1, __half* hdst,
                                        const int* idxd, const float* gx,
                                        const float* gy, const float* gz,
                                        const float* s_sc1, const float* s_sf1,
                                        int grp, int tid){
    int cpair = tid & 127;
    int c0    = cpair*2;
    int sbase = (tid >> 7) * 16;
    int b     = (grp*2) >> 11;
    int p     = kperm(c0);
    float wa0 = W1[c0*K1+0],     wa1 = W1[c0*K1+1],     wa2 = W1[c0*K1+2];
    float wb0 = W1[(c0+1)*K1+0], wb1 = W1[(c0+1)*K1+1], wb2 = W1[(c0+1)*K1+2];
    float sca = s_sc1[c0],   sfa = s_sf1[c0];
    float scb = s_sc1[c0+1], sfb = s_sf1[c0+1];
    const __half2* F1b2 = (const __half2*)(d_F1h + (size_t)b*Nn*OO);
    #pragma unroll 4
    for (int ds = 0; ds < 16; ds++){
        int s = sbase + ds;
        float2 f = __half22float2(F1b2[(size_t)idxd[s]*128 + cpair]);
        float va = fmaf(wa0, gx[s], fmaf(wa1, gy[s], fmaf(wa2, gz[s], f.x)));
        float vb = fmaf(wb0, gx[s], fmaf(wb1, gy[s], fmaf(wb2, gz[s], f.y)));
        va = fmaxf(fmaf(va, sca, sfa), 0.f);
        vb = fmaxf(fmaf(vb, scb, sfb), 0.f);
        *(__half2*)(hdst + s*HSTR + p) = __floats2half2_rn(va, vb);
    }
}

// ---------------- K4: persistent conv2, double-buffered h, register BN2 partials --------
__global__ void __launch_bounds__(512, 1) k_conv2(const float* __restrict__ xyz,
                                                  const float* __restrict__ rot,
                                                  const float* __restrict__ W1,
                                                  const float* __restrict__ gamma1,
                                                  const float* __restrict__ beta1){
    extern __shared__ __align__(16) char smraw[];
    __half* h16  = (__half*)smraw;                 // 2 x [64][HSTR]
    __half* Asm  = (__half*)(smraw + OFF_A);       // [256][HSTR]
    int*    idxb = (int*)(smraw + OFF_IDX);        // 2 x [64]
    float*  gbuf = (float*)(smraw + OFF_G);        // 2 x 3 x [64]
    float*  s_sc1 = (float*)(smraw + OFF_SC1);     // [256]
    float*  s_sf1 = (float*)(smraw + OFF_SF1);     // [256]

    int tid = threadIdx.x;
    int lane = tid & 31, w = tid >> 5;
    int q = lane & 3, g = lane >> 2;
    int obase = (w & 7) * 32;                      // 8 warp-cols cover 256 o
    int warpS = (w >> 3) * 32;                     // 2 warp-rows cover 64 s (= 2 bp)

    // ---- load ALL of W2 into smem once ----
    #pragma unroll
    for (int k = 0; k < 16; k++){
        int i = tid + k*512;
        int row = i >> 5, seg = i & 31;
        uint32_t d = (uint32_t)__cvta_generic_to_shared(Asm + row*HSTR + seg*8);
        asm volatile("cp.async.cg.shared.global [%0], [%1], 16;\n"
                     :: "r"(d), "l"(d_W2h + (size_t)row*Cc + seg*8));
    }
    asm volatile("cp.async.commit_group;\n" ::: "memory");

    // ---- fused BN1 final reduce (overlaps cp.async) ----
    if (tid < 256){
        float s = 0.f, qv = 0.f;
        #pragma unroll 8
        for (int z = 0; z < 32; z++){
            s  += d_pp[z*OO + tid];
            qv += d_pp[32*OO + z*OO + tid];
        }
        float mu  = s * INVCNT;
        float var = qv * INVCNT - mu*mu;
        float sc  = rsqrtf(var + EPSf) * gamma1[tid];
        s_sc1[tid] = sc;
        s_sf1[tid] = beta1[tid] - mu*sc;
    }

    const char* Arow = (const char*)(Asm + (size_t)(obase + g)*HSTR);
    const int NG = BP/2;                           // 4096 groups of 2 bp

    // register accumulators for global BN2 sums (per thread, fixed o set)
    float aS[2][2] = {{0.f,0.f},{0.f,0.f}};
    float aQ[2][2] = {{0.f,0.f},{0.f,0.f}};

    // prologue: geom(g0) ; sync ; hbuild(g0) + geom(g1) ; sync
    int g0 = blockIdx.x;
    geom2(xyz, rot, g0, tid, idxb, gbuf, gbuf+128, gbuf+256);
    __syncthreads();
    hbuild2(W1, h16, idxb, gbuf, gbuf+128, gbuf+256, s_sc1, s_sf1, g0, tid);
    if (g0 + NSM < NG)
        geom2(xyz, rot, g0 + NSM, tid, idxb+64, gbuf+64, gbuf+192, gbuf+320);
    asm volatile("cp.async.wait_group 0;\n" ::: "memory");
    __syncthreads();

    int par = 0;
    for (int gi = g0; gi < NG; gi += NSM){
        int np = par ^ 1;
        if (gi + NSM < NG)
            hbuild2(W1, h16 + np*64*HSTR, idxb + np*64,
                    gbuf + np*64, gbuf + 128 + np*64, gbuf + 256 + np*64,
                    s_sc1, s_sf1, gi + NSM, tid);
        if (gi + 2*NSM < NG)
            geom2(xyz, rot, gi + 2*NSM, tid, idxb + par*64,
                  gbuf + par*64, gbuf + 128 + par*64, gbuf + 256 + par*64);

        const char* Bsm = (const char*)(h16 + (size_t)par*64*HSTR + (size_t)(warpS + g)*HSTR);
        float acc[2][4][4];
        #pragma unroll
        for (int i = 0; i < 2; i++)
            #pragma unroll
            for (int j = 0; j < 4; j++)
                #pragma unroll
                for (int k = 0; k < 4; k++) acc[i][j][k] = 0.f;

        #pragma unroll 4
        for (int kt = 0; kt < 16; kt++){
            uint2 fa0 = *(const uint2*)(Arow +             0 + kt*32 + q*8);
            uint2 fa1 = *(const uint2*)(Arow +  8*HSTR*2      + kt*32 + q*8);
            uint2 fa2 = *(const uint2*)(Arow + 16*HSTR*2      + kt*32 + q*8);
            uint2 fa3 = *(const uint2*)(Arow + 24*HSTR*2      + kt*32 + q*8);
            #pragma unroll
            for (int j = 0; j < 4; j++){
                uint2 bv = *(const uint2*)(Bsm + j*(8*HSTR*2) + kt*32 + q*8);
                mma_f16(acc[0][j][0], acc[0][j][1], acc[0][j][2], acc[0][j][3],
                        fa0.x, fa1.x, fa0.y, fa1.y, bv.x, bv.y);
                mma_f16(acc[1][j][0], acc[1][j][1], acc[1][j][2], acc[1][j][3],
                        fa2.x, fa3.x, fa2.y, fa3.y, bv.x, bv.y);
            }
        }

        int bp = gi*2 + (w >> 3);
        #pragma unroll
        for (int i = 0; i < 2; i++){
            float s0=0.f, q0=0.f, mx0=-3.4e38f, mn0=3.4e38f;
            float s1=0.f, q1=0.f, mx1=-3.4e38f, mn1=3.4e38f;
            #pragma unroll
            for (int j4 = 0; j4 < 4; j4++){
                const float* a = acc[i][j4];
                s0 += a[0] + a[1];
                q0  = fmaf(a[0], a[0], fmaf(a[1], a[1], q0));
                mx0 = fmaxf(mx0, fmaxf(a[0], a[1]));
                mn0 = fminf(mn0, fminf(a[0], a[1]));
                s1 += a[2] + a[3];
                q1  = fmaf(a[2], a[2], fmaf(a[3], a[3], q1));
                mx1 = fmaxf(mx1, fmaxf(a[2], a[3]));
                mn1 = fminf(mn1, fminf(a[2], a[3]));
            }
            #pragma unroll
            for (int msk = 1; msk <= 2; msk <<= 1){
                s0 += __shfl_xor_sync(0xffffffffu, s0, msk);
                q0 += __shfl_xor_sync(0xffffffffu, q0, msk);
                mx0 = fmaxf(mx0, __shfl_xor_sync(0xffffffffu, mx0, msk));
                mn0 = fminf(mn0, __shfl_xor_sync(0xffffffffu, mn0, msk));
                s1 += __shfl_xor_sync(0xffffffffu, s1, msk);
                q1 += __shfl_xor_sync(0xffffffffu, q1, msk);
                mx1 = fmaxf(mx1, __shfl_xor_sync(0xffffffffu, mx1, msk));
                mn1 = fminf(mn1, __shfl_xor_sync(0xffffffffu, mn1, msk));
            }
            aS[i][0] += s0;  aQ[i][0] += q0;
            aS[i][1] += s1;  aQ[i][1] += q1;
            if (q == 0){
                int o0 = obase + 16*i + g;
                size_t ix0 = (size_t)bp*OO + o0;
                d_mx2[ix0] = mx0; d_mn2[ix0] = mn0;
                d_mx2[ix0 + 8] = mx1; d_mn2[ix0 + 8] = mn1;
            }
        }
        __syncthreads();
        par = np;
    }

    // write block-level BN2 partials (296 x 256)
    if (q == 0){
        int zrow = blockIdx.x*2 + (w >> 3);
        #pragma unroll
        for (int i = 0; i < 2; i++){
            int o0 = obase + 16*i + g;
            d_p2s[zrow*OO + o0]     = aS[i][0];
            d_p2q[zrow*OO + o0]     = aQ[i][0];
            d_p2s[zrow*OO + o0 + 8] = aS[i][1];
            d_p2q[zrow*OO + o0 + 8] = aQ[i][1];
        }
    }
}

// ---------------- K5: BN2 final reduce + relu + max via monotonicity ----------------
__global__ void __launch_bounds__(256) k_final(const float* __restrict__ gamma,
                                               const float* __restrict__ beta,
                                               float* __restrict__ out){
    int blk = blockIdx.x;                 // 256 blocks, 32 p's each
    int bp0 = blk * 32;
    int b = bp0 >> 11;
    int pbase = bp0 & 2047;
    int tid = threadIdx.x;
    __shared__ float sh[256*33];

    int o = tid;
    float s = 0.f, qv = 0.f;
    #pragma unroll
    for (int z = 0; z < 8; z++){
        s  += d_pp[2*(32*OO) + z*OO + o];
        qv += d_pp[3*(32*OO) + z*OO + o];
    }
    float mu  = s * INVCNT;
    float var = qv * INVCNT - mu*mu;
    float sc  = rsqrtf(var + EPSf) * gamma[o];
    float sf  = beta[o] - mu*sc;

    for (int p = 0; p < 32; p++){
        size_t ix = (size_t)(bp0 + p)*OO + o;
        float mx = d_mx2[ix], mn = d_mn2[ix];
        float m = (sc >= 0.f) ? mx : mn;
        sh[o*33 + p] = fmaxf(fmaf(m, sc, sf), 0.f);
    }
    __syncthreads();

    int p   = tid & 31;
    int og0 = (tid >> 5) * 32;
    #pragma unroll
    for (int k = 0; k < 32; k++){
        int o2 = og0 + k;
        out[((size_t)(b*OO + o2))*Nn + pbase + p] = sh[o2*33 + p];
    }
}

// ---------------- launcher ----------------
extern "C" void kernel_launch(void* const* d_in, const int* in_sizes, int n_in,
                              void* d_out, int out_size){
    (void)in_sizes; (void)n_in; (void)out_size;
    const float* xyz  = (const float*)d_in[0];
    const float* feat = (const float*)d_in[1];
    const float* rot  = (const float*)d_in[2];
    const float* W1   = (const float*)d_in[3];
    const float* g1   = (const float*)d_in[4];
    const float* b1   = (const float*)d_in[5];
    const float* W2   = (const float*)d_in[6];
    const float* g2   = (const float*)d_in[7];
    const float* b2   = (const float*)d_in[8];
    float* out = (float*)d_out;

    static bool s_init = false;
    static cudaStream_t s2;
    static cudaEvent_t evA, evB;
    if (!s_init){
        cudaStreamCreateWithFlags(&s2, cudaStreamNonBlocking);
        cudaEventCreateWithFlags(&evA, cudaEventDisableTiming);
        cudaEventCreateWithFlags(&evB, cudaEventDisableTiming);
        cudaFuncSetAttribute(k_conv2, cudaFuncAttributeMaxDynamicSharedMemorySize, SMEMB);
        cudaFuncSetAttribute(k_F1mma, cudaFuncAttributeMaxDynamicSharedMemorySize, F1_SMEM);
        s_init = true;
    }

    // fork: k_idx on side stream, concurrent with weight prep + F1 GEMM
    cudaEventRecord(evA, 0);
    cudaStreamWaitEvent(s2, evA, 0);
    k_idx<<<BP/8, 256, 0, s2>>>(xyz, rot);
    cudaEventRecord(evB, s2);

    k_wtr  <<<256 + 2048, 256>>>(W1, W2, feat);
    k_F1mma<<<128, 256, F1_SMEM>>>();

    // join: stats1 needs idx + F1
    cudaStreamWaitEvent(0, evB, 0);

    k_stats1<<<BP/2, 256>>>(xyz, rot, W1);
    k_red_a <<<dim3(32,2), 256>>>();
    k_conv2 <<<NSM, 512, SMEMB>>>(xyz, rot, W1, g1, b1);
    k_red2p <<<8, 256>>>();
    k_final <<<BP/32, 256>>>(g2, b2, out);
}